// round 5
// baseline (speedup 1.0000x reference)
#include <cuda_runtime.h>

// OrdinalPooling2D: x (32,112,112,128) f32 NHWC, 2x2 stride-2 pool,
// sort 4 window values descending, dot with per-channel weights w[128,4]
// (relu + renormalize). Output (32,56,56,128) f32.
//
// R4 re-bench (prior attempt hit infra failure): 128-thread blocks (finer
// occupancy granularity), 2D grid with zero per-thread div/mod, 32-bit
// addressing. Keeps the 8 front-batched LDG.128 per thread + amortized
// weight normalize + streaming cache hints.

#define N_B   32
#define H_IN  112
#define W_IN  112
#define H_OUT 56
#define W_OUT 56
#define C_CH  128
#define C4    (C_CH / 4)          // 32 float4 groups per position
#define WO2   (W_OUT / 2)         // 28 output-pair positions per row

#define THREADS 128               // 4 wo2-pairs x 32 channel-groups
#define GRID_X  (WO2 / 4)         // 7 blocks cover a row's 28 wo2 pairs
#define GRID_Y  (N_B * H_OUT)     // 1792 (n, ho) rows

// sort 4 values descending + dot with pre-normalized weights
__device__ __forceinline__ float ord_one(float p0, float p1, float p2, float p3,
                                         float w0, float w1, float w2, float w3) {
    float t;
#define CE(a, b) t = fmaxf(a, b); b = fminf(a, b); a = t;
    CE(p0, p1); CE(p2, p3);
    CE(p1, p2);
    CE(p0, p1); CE(p2, p3);
    CE(p1, p2);
#undef CE
    return p0 * w0 + p1 * w1 + p2 * w2 + p3 * w3;
}

__global__ __launch_bounds__(THREADS)
void ordinal_pool_kernel(const float4* __restrict__ x,
                         const float4* __restrict__ w4,   // w[C,4]: one float4 per channel
                         float4* __restrict__ out) {
    int tid = threadIdx.x;
    int c4  = tid & (C4 - 1);                     // channel group
    int wo2 = blockIdx.x * 4 + (tid >> 5);        // output-pair column
    int y   = blockIdx.y;                          // n*H_OUT + ho (uniform)
    int n   = y / H_OUT;
    int ho  = y - n * H_OUT;

    // 32-bit indices: x has 12.85M float4, out 3.2M float4 — both fit int.
    int base = ((n * H_IN + 2 * ho) * W_IN + 4 * wo2) * C4 + c4;
    const int ROW = W_IN * C4;
    int oidx = (y * W_OUT + 2 * wo2) * C4 + c4;   // y == n*H_OUT+ho

    // 8 independent streaming loads, front-batched
    float4 a0 = __ldcs(x + base);
    float4 b0 = __ldcs(x + base + C4);
    float4 a1 = __ldcs(x + base + 2 * C4);
    float4 b1 = __ldcs(x + base + 3 * C4);
    float4 c0 = __ldcs(x + base + ROW);
    float4 d0 = __ldcs(x + base + ROW + C4);
    float4 c1 = __ldcs(x + base + ROW + 2 * C4);
    float4 d1 = __ldcs(x + base + ROW + 3 * C4);

    // weights for channels 4*c4 .. 4*c4+3 (2KB table, cached) — shared by both positions
    int ch = c4 * 4;
    float4 wa = __ldg(&w4[ch + 0]);
    float4 wb = __ldg(&w4[ch + 1]);
    float4 wc = __ldg(&w4[ch + 2]);
    float4 wd = __ldg(&w4[ch + 3]);

    // relu + renormalize, once per channel
#define NORM(W) { \
        W.x = fmaxf(W.x, 0.0f); W.y = fmaxf(W.y, 0.0f); \
        W.z = fmaxf(W.z, 0.0f); W.w = fmaxf(W.w, 0.0f); \
        float inv = __frcp_rn(W.x + W.y + W.z + W.w);    \
        W.x *= inv; W.y *= inv; W.z *= inv; W.w *= inv; }
    NORM(wa) NORM(wb) NORM(wc) NORM(wd)
#undef NORM

    float4 o0, o1;
    o0.x = ord_one(a0.x, b0.x, c0.x, d0.x, wa.x, wa.y, wa.z, wa.w);
    o0.y = ord_one(a0.y, b0.y, c0.y, d0.y, wb.x, wb.y, wb.z, wb.w);
    o0.z = ord_one(a0.z, b0.z, c0.z, d0.z, wc.x, wc.y, wc.z, wc.w);
    o0.w = ord_one(a0.w, b0.w, c0.w, d0.w, wd.x, wd.y, wd.z, wd.w);

    o1.x = ord_one(a1.x, b1.x, c1.x, d1.x, wa.x, wa.y, wa.z, wa.w);
    o1.y = ord_one(a1.y, b1.y, c1.y, d1.y, wb.x, wb.y, wb.z, wb.w);
    o1.z = ord_one(a1.z, b1.z, c1.z, d1.z, wc.x, wc.y, wc.z, wc.w);
    o1.w = ord_one(a1.w, b1.w, c1.w, d1.w, wd.x, wd.y, wd.z, wd.w);

    __stcs(out + oidx, o0);
    __stcs(out + oidx + C4, o1);
}

extern "C" void kernel_launch(void* const* d_in, const int* in_sizes, int n_in,
                              void* d_out, int out_size) {
    const float4* x  = (const float4*)d_in[0];   // x: 32*112*112*128 f32
    const float4* w4 = (const float4*)d_in[1];   // ordinal_weights: 128*4 f32
    float4* out = (float4*)d_out;

    dim3 grid(GRID_X, GRID_Y);
    ordinal_pool_kernel<<<grid, THREADS>>>(x, w4, out);
}

// round 6
// speedup vs baseline: 1.1136x; 1.1136x over previous
#include <cuda_runtime.h>

// OrdinalPooling2D: x (32,112,112,128) f32 NHWC, 2x2 stride-2 pool,
// sort 4 window values descending, dot with per-channel weights w[128,4]
// (relu + renormalize). Output (32,56,56,128) f32.
//
// R6: 4 output wo positions per thread -> 16 front-batched LDG.128
// (two 4KB-contiguous spans per warp), weight normalize amortized x4,
// 4 contiguous stores. Block = 4 warps, each warp owns one ho row.

#define N_B   32
#define H_IN  112
#define W_IN  112
#define H_OUT 56
#define W_OUT 56
#define C_CH  128
#define C4    (C_CH / 4)          // 32 float4 groups per position

#define THREADS 128
#define GRID_X  (W_OUT / 4)       // 14 wo-quads
#define GRID_Y  (N_B * H_OUT / 4) // 448 row-quads (4 ho rows per block, one per warp)

// sort 4 values descending + dot with pre-normalized weights
__device__ __forceinline__ float ord_one(float p0, float p1, float p2, float p3,
                                         float w0, float w1, float w2, float w3) {
    float t;
#define CE(a, b) t = fmaxf(a, b); b = fminf(a, b); a = t;
    CE(p0, p1); CE(p2, p3);
    CE(p1, p2);
    CE(p0, p1); CE(p2, p3);
    CE(p1, p2);
#undef CE
    return p0 * w0 + p1 * w1 + p2 * w2 + p3 * w3;
}

__global__ __launch_bounds__(THREADS)
void ordinal_pool_kernel(const float4* __restrict__ x,
                         const float4* __restrict__ w4,   // w[C,4]: one float4 per channel
                         float4* __restrict__ out) {
    int tid  = threadIdx.x;
    int c4   = tid & (C4 - 1);                 // channel group (lane)
    int wrow = tid >> 5;                       // warp id 0..3 -> ho offset

    // row-quad: 4 consecutive ho within one image (H_OUT % 4 == 0)
    int yq  = blockIdx.y;                      // n*(H_OUT/4) + ho4
    int n   = yq / (H_OUT / 4);
    int ho  = (yq - n * (H_OUT / 4)) * 4 + wrow;
    int wo0 = blockIdx.x * 4;                  // first of 4 output columns

    // 32-bit indices (x: 12.85M float4, out: 3.2M float4 — fit in int)
    int base = ((n * H_IN + 2 * ho) * W_IN + 2 * wo0) * C4 + c4;
    const int ROW = W_IN * C4;
    int oidx = ((n * H_OUT + ho) * W_OUT + wo0) * C4 + c4;

    // 16 independent streaming loads, front-batched.
    // Row r=2ho: 8 consecutive input positions (4KB contiguous per warp).
    float4 a0 = __ldcs(x + base + 0 * C4);
    float4 b0 = __ldcs(x + base + 1 * C4);
    float4 a1 = __ldcs(x + base + 2 * C4);
    float4 b1 = __ldcs(x + base + 3 * C4);
    float4 a2 = __ldcs(x + base + 4 * C4);
    float4 b2 = __ldcs(x + base + 5 * C4);
    float4 a3 = __ldcs(x + base + 6 * C4);
    float4 b3 = __ldcs(x + base + 7 * C4);
    // Row 2ho+1
    float4 c0 = __ldcs(x + base + ROW + 0 * C4);
    float4 d0 = __ldcs(x + base + ROW + 1 * C4);
    float4 c1 = __ldcs(x + base + ROW + 2 * C4);
    float4 d1 = __ldcs(x + base + ROW + 3 * C4);
    float4 c2 = __ldcs(x + base + ROW + 4 * C4);
    float4 d2 = __ldcs(x + base + ROW + 5 * C4);
    float4 c3 = __ldcs(x + base + ROW + 6 * C4);
    float4 d3 = __ldcs(x + base + ROW + 7 * C4);

    // weights for channels 4*c4 .. 4*c4+3 (2KB table) — shared by all 4 positions
    int ch = c4 * 4;
    float4 wa = __ldg(&w4[ch + 0]);
    float4 wb = __ldg(&w4[ch + 1]);
    float4 wc = __ldg(&w4[ch + 2]);
    float4 wd = __ldg(&w4[ch + 3]);

#define NORM(W) { \
        W.x = fmaxf(W.x, 0.0f); W.y = fmaxf(W.y, 0.0f); \
        W.z = fmaxf(W.z, 0.0f); W.w = fmaxf(W.w, 0.0f); \
        float inv = __frcp_rn(W.x + W.y + W.z + W.w);    \
        W.x *= inv; W.y *= inv; W.z *= inv; W.w *= inv; }
    NORM(wa) NORM(wb) NORM(wc) NORM(wd)
#undef NORM

#define POS(O, A, B, C, D) \
    O.x = ord_one(A.x, B.x, C.x, D.x, wa.x, wa.y, wa.z, wa.w); \
    O.y = ord_one(A.y, B.y, C.y, D.y, wb.x, wb.y, wb.z, wb.w); \
    O.z = ord_one(A.z, B.z, C.z, D.z, wc.x, wc.y, wc.z, wc.w); \
    O.w = ord_one(A.w, B.w, C.w, D.w, wd.x, wd.y, wd.z, wd.w);

    float4 o0, o1, o2, o3;
    POS(o0, a0, b0, c0, d0)
    POS(o1, a1, b1, c1, d1)
    POS(o2, a2, b2, c2, d2)
    POS(o3, a3, b3, c3, d3)
#undef POS

    __stcs(out + oidx + 0 * C4, o0);
    __stcs(out + oidx + 1 * C4, o1);
    __stcs(out + oidx + 2 * C4, o2);
    __stcs(out + oidx + 3 * C4, o3);
}

extern "C" void kernel_launch(void* const* d_in, const int* in_sizes, int n_in,
                              void* d_out, int out_size) {
    const float4* x  = (const float4*)d_in[0];   // x: 32*112*112*128 f32
    const float4* w4 = (const float4*)d_in[1];   // ordinal_weights: 128*4 f32
    float4* out = (float4*)d_out;

    dim3 grid(GRID_X, GRID_Y);
    ordinal_pool_kernel<<<grid, THREADS>>>(x, w4, out);
}